// round 11
// baseline (speedup 1.0000x reference)
#include <cuda_runtime.h>
#include <cuda_bf16.h>
#include <math.h>
#include <stdint.h>

// ---------------------------------------------------------------------------
// Problem constants
// ---------------------------------------------------------------------------
#define BATCH   2
#define NQ      8192
#define EMBED   256
#define HEADS   8
#define DH      32
#define LEVELS  3
#define POINTS  4
#define NV      6300
#define BQ      (BATCH * NQ)   // 16384
#define MV      (BATCH * NV)   // 12600

// ---------------------------------------------------------------------------
// Scratch (device globals)
// ---------------------------------------------------------------------------
__device__ float          g_qn  [BQ * EMBED];   // LN1(query), fp32
__device__ __nv_bfloat16  g_qa  [BQ * EMBED];   // bf16(qn + query_pos)
__device__ float          g_oa  [BQ * 288];     // [offsets(192) | logits(96)] per row
__device__ __nv_bfloat16  g_vr  [MV * EMBED];   // bf16(value)
__device__ __nv_bfloat16  g_v   [MV * EMBED];   // bf16(value @ Wv + bv)
__device__ __nv_bfloat16  g_samp[BQ * EMBED];   // bf16 sampled output
__device__ float          g_q   [BQ * EMBED];
__device__ __nv_bfloat16  g_q2  [BQ * EMBED];   // bf16(LN2(q))
__device__ __nv_bfloat16  g_hid [BQ * 1024];    // bf16(gelu(...))
__device__ __nv_bfloat16  g_WT  [729088];       // transposed weights [N][K], bf16
__device__ float          g_boa [288];          // concat(bo, ba)

#define WT_OA  0        // 288 x 256  (Wo^T rows 0..191, Wa^T rows 192..287)
#define WT_V   73728    // 256 x 256
#define WT_P   139264   // 256 x 256
#define WT_F1  204800   // 1024 x 256
#define WT_F2  466944   // 256 x 1024

// ---------------------------------------------------------------------------
// Helpers
// ---------------------------------------------------------------------------
__device__ __forceinline__ uint32_t smem_u32(const void* p) {
    uint32_t a;
    asm("{ .reg .u64 t; cvta.to.shared.u64 t, %1; cvt.u32.u64 %0, t; }"
        : "=r"(a) : "l"(p));
    return a;
}
#define CP_ASYNC16(dst, src, sz) \
    asm volatile("cp.async.cg.shared.global [%0], [%1], 16, %2;" \
                 :: "r"(dst), "l"(src), "r"(sz) : "memory")
#define CP_COMMIT() asm volatile("cp.async.commit_group;" ::: "memory")
#define CP_WAIT1()  asm volatile("cp.async.wait_group 1;" ::: "memory")
#define CP_WAIT0()  asm volatile("cp.async.wait_group 0;" ::: "memory")

#define LDSM_X4(r0, r1, r2, r3, addr) \
    asm volatile("ldmatrix.sync.aligned.m8n8.x4.shared.b16 {%0,%1,%2,%3}, [%4];" \
                 : "=r"(r0), "=r"(r1), "=r"(r2), "=r"(r3) : "r"(addr))

__device__ __forceinline__ void mma_bf16(float* c, const uint32_t* a, const uint32_t* b) {
    asm volatile(
        "mma.sync.aligned.m16n8k16.row.col.f32.bf16.bf16.f32 "
        "{%0,%1,%2,%3}, {%4,%5,%6,%7}, {%8,%9}, {%0,%1,%2,%3};"
        : "+f"(c[0]), "+f"(c[1]), "+f"(c[2]), "+f"(c[3])
        : "r"(a[0]), "r"(a[1]), "r"(a[2]), "r"(a[3]), "r"(b[0]), "r"(b[1]));
}

// ---------------------------------------------------------------------------
// Weight transpose + bf16 round: WT[n][k] = bf16(W[k][n])
// ---------------------------------------------------------------------------
__global__ void transpose_all(const float* __restrict__ W0, const float* __restrict__ W1,
                              const float* __restrict__ W2, const float* __restrict__ W3,
                              const float* __restrict__ W4, const float* __restrict__ W5,
                              __nv_bfloat16* __restrict__ WT)
{
    __shared__ float t[32][33];
    const int seg = blockIdx.z;
    const int Ks[6]  = {256, 256, 256, 256, 256, 1024};
    const int Ns[6]  = {192,  96, 256, 256, 1024, 256};
    const int Off[6] = {WT_OA, WT_OA + 192 * 256, WT_V, WT_P, WT_F1, WT_F2};
    const float* src = seg == 0 ? W0 : seg == 1 ? W1 : seg == 2 ? W2 :
                       seg == 3 ? W3 : seg == 4 ? W4 : W5;
    const int K = Ks[seg], N = Ns[seg];
    __nv_bfloat16* dst = WT + Off[seg];

    int bx = blockIdx.x * 32;
    int by = blockIdx.y * 32;
    if (bx >= N || by >= K) return;

    int x = bx + threadIdx.x;
#pragma unroll
    for (int j = 0; j < 32; j += 8) {
        int y = by + threadIdx.y + j;
        if (x < N && y < K) t[threadIdx.y + j][threadIdx.x] = src[(size_t)y * N + x];
    }
    __syncthreads();
    x = by + threadIdx.x;
#pragma unroll
    for (int j = 0; j < 32; j += 8) {
        int y = bx + threadIdx.y + j;
        if (x < K && y < N)
            dst[(size_t)y * K + x] = __float2bfloat16_rn(t[threadIdx.x][threadIdx.y + j]);
    }
}

// Round value input to bf16; also build concat bias for the fused Wo|Wa GEMM
__global__ void round_kernel(const float* __restrict__ src,
                             __nv_bfloat16* __restrict__ dst, int n,
                             const float* __restrict__ bo,
                             const float* __restrict__ ba,
                             float* __restrict__ boa)
{
    int i = blockIdx.x * blockDim.x + threadIdx.x;
    if (i < n) dst[i] = __float2bfloat16_rn(src[i]);
    if (i < 288) boa[i] = (i < 192) ? bo[i] : ba[i - 192];
}

// ---------------------------------------------------------------------------
// bf16 HMMA GEMM. CTA = 128 threads, tile 128(M) x 128(N).
// 4 warps, each computing a 64x64 sub-tile (2x2 warp grid) -> 128 B of
// smem-fragment traffic per MMA (vs 192 at 64x32), since A-frags are shared
// by 2 warps and B-frags by 2 warps.
// 3-stage cp.async pipeline, BK=32, 80B-padded smem rows.
// ---------------------------------------------------------------------------
#define ABYTES   10240                  // 128 rows * 80B
#define STG      20480                  // A + B per stage
#define SM_BYTES (3 * STG)              // 61440

__global__ __launch_bounds__(128) void gemm_bf16(
    const __nv_bfloat16* __restrict__ A, const __nv_bfloat16* __restrict__ WT,
    const float* __restrict__ bias, const float* __restrict__ add1,
    const float* __restrict__ add2, float* __restrict__ Cf,
    __nv_bfloat16* __restrict__ Cb, int M, int N, int K, int gelu_flag)
{
    extern __shared__ char smem[];
    const uint32_t sbase = smem_u32(smem);
    const int tid  = threadIdx.x;
    const int wid  = tid >> 5;
    const int lane = tid & 31;
    const int wm   = wid >> 1;          // 0..1 -> 64-row slice
    const int wn   = wid & 1;           // 0..1 -> 64-col slice
    const int m0   = blockIdx.y * 128;
    const int n0   = blockIdx.x * 128;

    float acc[4][8][4];
#pragma unroll
    for (int i = 0; i < 4; i++)
#pragma unroll
        for (int j = 0; j < 8; j++)
#pragma unroll
            for (int r = 0; r < 4; r++) acc[i][j][r] = 0.f;

    const int nk = K >> 5;

    auto load_tile = [&](int s, int kt) {
        const int k0 = kt * 32;
        const uint32_t base = sbase + (uint32_t)(s * STG);
        // A: 128 rows x 4 chunks(16B) = 512, 4 iters of 128 threads
#pragma unroll
        for (int t = 0; t < 4; t++) {
            int idx = tid + t * 128;
            int row = idx >> 2, c = idx & 3;
            int gm = m0 + row;
            int sz = (gm < M) ? 16 : 0;
            const __nv_bfloat16* src = A + (size_t)(sz ? gm : 0) * K + k0 + c * 8;
            CP_ASYNC16(base + (uint32_t)(row * 80 + c * 16), src, sz);
        }
        // B: 128 rows x 4 chunks = 512, 4 iters
#pragma unroll
        for (int t = 0; t < 4; t++) {
            int idx = tid + t * 128;
            int row = idx >> 2, c = idx & 3;
            int gn = n0 + row;
            int sz = (gn < N) ? 16 : 0;
            const __nv_bfloat16* src = WT + (size_t)(sz ? gn : 0) * K + k0 + c * 8;
            CP_ASYNC16(base + (uint32_t)(ABYTES + row * 80 + c * 16), src, sz);
        }
    };

    load_tile(0, 0); CP_COMMIT();
    load_tile(1, 1); CP_COMMIT();

    const int quad = lane >> 3;
    const int qr   = lane & 7;

    int s = 0;
    for (int kt = 0; kt < nk; kt++) {
        if (kt + 1 < nk) { CP_WAIT1(); } else { CP_WAIT0(); }
        __syncthreads();

        if (kt + 2 < nk) {
            load_tile((s + 2 >= 3) ? s - 1 : s + 2, kt + 2);
            CP_COMMIT();
        }

        const uint32_t abase = sbase + (uint32_t)(s * STG);
        const uint32_t bbase = abase + ABYTES;

#pragma unroll
        for (int ks = 0; ks < 2; ks++) {
            const int k0 = ks * 16;
            uint32_t a[4][4];
#pragma unroll
            for (int mi = 0; mi < 4; mi++) {
                int mrow = wm * 64 + mi * 16 + (quad & 1) * 8 + qr;
                uint32_t addr = abase + (uint32_t)(mrow * 80 + (k0 + (quad >> 1) * 8) * 2);
                LDSM_X4(a[mi][0], a[mi][1], a[mi][2], a[mi][3], addr);
            }
            uint32_t b[8][2];
#pragma unroll
            for (int nj = 0; nj < 4; nj++) {
                int nrow = wn * 64 + nj * 16 + ((quad >> 1) & 1) * 8 + qr;
                uint32_t addr = bbase + (uint32_t)(nrow * 80 + (k0 + (quad & 1) * 8) * 2);
                LDSM_X4(b[nj * 2][0], b[nj * 2][1], b[nj * 2 + 1][0], b[nj * 2 + 1][1], addr);
            }
#pragma unroll
            for (int mi = 0; mi < 4; mi++)
#pragma unroll
                for (int ni = 0; ni < 8; ni++)
                    mma_bf16(acc[mi][ni], a[mi], b[ni]);
        }
        s = (s + 1 >= 3) ? 0 : s + 1;
    }

    // ---- epilogue ----
    const int g = lane >> 2;
    const int c2 = lane & 3;
#pragma unroll
    for (int mi = 0; mi < 4; mi++) {
#pragma unroll
        for (int ni = 0; ni < 8; ni++) {
            int row = m0 + wm * 64 + mi * 16 + g;
            int col = n0 + wn * 64 + ni * 8 + c2 * 2;
            if (col >= N) continue;
            float2 bs = *(const float2*)&bias[col];
#pragma unroll
            for (int half = 0; half < 2; half++) {
                int r = row + half * 8;
                if (r >= M) continue;
                size_t idx = (size_t)r * N + col;
                float vx = acc[mi][ni][half * 2 + 0] + bs.x;
                float vy = acc[mi][ni][half * 2 + 1] + bs.y;
                if (add1) {
                    float2 a1 = *(const float2*)&add1[idx];
                    vx += a1.x; vy += a1.y;
                }
                if (add2) {
                    float2 a2 = *(const float2*)&add2[idx];
                    vx += a2.x; vy += a2.y;
                }
                if (gelu_flag) {
                    vx = 0.5f * vx * (1.f + erff(vx * 0.70710678118654752f));
                    vy = 0.5f * vy * (1.f + erff(vy * 0.70710678118654752f));
                }
                if (Cf) {
                    float2 o; o.x = vx; o.y = vy;
                    *(float2*)&Cf[idx] = o;
                } else {
                    __nv_bfloat162 o;
                    o.x = __float2bfloat16_rn(vx);
                    o.y = __float2bfloat16_rn(vy);
                    *(__nv_bfloat162*)&Cb[idx] = o;
                }
            }
        }
    }
}

// ---------------------------------------------------------------------------
// LayerNorm: one warp per row of 256.
// ---------------------------------------------------------------------------
__global__ void ln_kernel(const float* __restrict__ x,
                          const float* __restrict__ gamma,
                          const float* __restrict__ beta,
                          const float* __restrict__ pos,
                          float* __restrict__ out_f,
                          __nv_bfloat16* __restrict__ out_b)
{
    int warp = (blockIdx.x * blockDim.x + threadIdx.x) >> 5;
    int lane = threadIdx.x & 31;
    if (warp >= BQ) return;

    const float* xr = x + (size_t)warp * EMBED;
    float v[8];
    float s = 0.f;
#pragma unroll
    for (int i = 0; i < 8; i++) { v[i] = xr[i * 32 + lane]; s += v[i]; }
#pragma unroll
    for (int o = 16; o > 0; o >>= 1) s += __shfl_xor_sync(0xFFFFFFFFu, s, o);
    float mean = s * (1.f / EMBED);

    float s2 = 0.f;
#pragma unroll
    for (int i = 0; i < 8; i++) { float d = v[i] - mean; s2 += d * d; }
#pragma unroll
    for (int o = 16; o > 0; o >>= 1) s2 += __shfl_xor_sync(0xFFFFFFFFu, s2, o);
    float rstd = rsqrtf(s2 * (1.f / EMBED) + 1e-5f);

    size_t base = (size_t)warp * EMBED;
#pragma unroll
    for (int i = 0; i < 8; i++) {
        int c = i * 32 + lane;
        float nv = (v[i] - mean) * rstd * gamma[c] + beta[c];
        if (out_f) out_f[base + c] = nv;
        if (out_b) {
            float ov = pos ? (nv + pos[base + c]) : nv;
            out_b[base + c] = __float2bfloat16_rn(ov);
        }
    }
}

// ---------------------------------------------------------------------------
// Deformable sampling, fused softmax, bf16 value, pair-of-points scheme.
// ---------------------------------------------------------------------------
__global__ void sample_kernel(const __nv_bfloat16* __restrict__ v,
                              const float* __restrict__ oa,
                              const float* __restrict__ ref,
                              __nv_bfloat16* __restrict__ out)
{
    const int LH[3] = {60, 30, 15};
    const int LW[3] = {80, 40, 20};
    const int LS[3] = {0, 4800, 6000};

    int warp = (blockIdx.x * blockDim.x + threadIdx.x) >> 5;
    int lane = threadIdx.x & 31;
    if (warp >= BQ * HEADS) return;

    int h  = warp & 7;
    int bq = warp >> 3;
    int b  = bq / NQ;

    const float* row  = oa + (size_t)bq * 288;
    const float* offr = row + h * 24;
    const float* lg   = row + 192 + h * 12;
    const float* refr = ref + (size_t)bq * (LEVELS * 2);

    float w[12];
    float mx = -1e30f;
#pragma unroll
    for (int i = 0; i < 12; i++) { w[i] = lg[i]; mx = fmaxf(mx, w[i]); }
    float ssum = 0.f;
#pragma unroll
    for (int i = 0; i < 12; i++) { w[i] = __expf(w[i] - mx); ssum += w[i]; }
    float inv = 1.f / ssum;

    const int gg = lane >> 4;
    const int li = lane & 15;

    float ax = 0.f, ay = 0.f;

#pragma unroll
    for (int j = 0; j < 6; j++) {
        const int l = j >> 1;
        const int p = 2 * (j & 1) + gg;
        const int Hl = LH[l], Wl = LW[l];

        float gx = refr[l * 2 + 0] * (float)Wl - 0.5f + offr[l * 8 + p * 2 + 0];
        float gy = refr[l * 2 + 1] * (float)Hl - 0.5f + offr[l * 8 + p * 2 + 1];
        float x0f = floorf(gx), y0f = floorf(gy);
        float wx = gx - x0f, wy = gy - y0f;
        int x0 = (int)x0f, y0 = (int)y0f;

        float w00 = (1.f - wx) * (1.f - wy);
        float w10 = wx * (1.f - wy);
        float w01 = (1.f - wx) * wy;
        float w11 = wx * wy;

        bool xv0 = (x0 >= 0) & (x0 < Wl);
        bool xv1 = (x0 + 1 >= 0) & (x0 + 1 < Wl);
        bool yv0 = (y0 >= 0) & (y0 < Hl);
        bool yv1 = (y0 + 1 >= 0) & (y0 + 1 < Hl);

        const __nv_bfloat16* vb = v + (((size_t)b * NV + LS[l]) * EMBED) + h * DH + 2 * li;

        float sx = 0.f, sy = 0.f;
        if (xv0 & yv0) {
            float2 c = __bfloat1622float2(*(const __nv_bfloat162*)(vb + (size_t)(y0 * Wl + x0) * EMBED));
            sx += w00 * c.x; sy += w00 * c.y;
        }
        if (xv1 & yv0) {
            float2 c = __bfloat1622float2(*(const __nv_bfloat162*)(vb + (size_t)(y0 * Wl + x0 + 1) * EMBED));
            sx += w10 * c.x; sy += w10 * c.y;
        }
        if (xv0 & yv1) {
            float2 c = __bfloat1622float2(*(const __nv_bfloat162*)(vb + (size_t)((y0 + 1) * Wl + x0) * EMBED));
            sx += w01 * c.x; sy += w01 * c.y;
        }
        if (xv1 & yv1) {
            float2 c = __bfloat1622float2(*(const __nv_bfloat162*)(vb + (size_t)((y0 + 1) * Wl + x0 + 1) * EMBED));
            sx += w11 * c.x; sy += w11 * c.y;
        }

        float wt = w[l * 4 + p] * inv;
        ax = fmaf(wt, sx, ax);
        ay = fmaf(wt, sy, ay);
    }

    ax += __shfl_xor_sync(0xFFFFFFFFu, ax, 16);
    ay += __shfl_xor_sync(0xFFFFFFFFu, ay, 16);

    if (gg == 0) {
        __nv_bfloat162 o;
        o.x = __float2bfloat16_rn(ax);
        o.y = __float2bfloat16_rn(ay);
        *(__nv_bfloat162*)&out[(size_t)bq * EMBED + h * DH + 2 * li] = o;
    }
}

// ---------------------------------------------------------------------------
// Launch
// ---------------------------------------------------------------------------
extern "C" void kernel_launch(void* const* d_in, const int* in_sizes, int n_in,
                              void* d_out, int out_size)
{
    (void)in_sizes; (void)n_in; (void)out_size;

    const float* query = (const float*)d_in[0];
    const float* value = (const float*)d_in[1];
    const float* qpos  = (const float*)d_in[2];
    const float* refp  = (const float*)d_in[3];
    const float* g1  = (const float*)d_in[6];
    const float* b1  = (const float*)d_in[7];
    const float* Wo  = (const float*)d_in[8];
    const float* bo  = (const float*)d_in[9];
    const float* Wa  = (const float*)d_in[10];
    const float* ba  = (const float*)d_in[11];
    const float* Wv  = (const float*)d_in[12];
    const float* bv  = (const float*)d_in[13];
    const float* Wp  = (const float*)d_in[14];
    const float* bp  = (const float*)d_in[15];
    const float* g2  = (const float*)d_in[16];
    const float* b2  = (const float*)d_in[17];
    const float* Wf1 = (const float*)d_in[18];
    const float* bf1 = (const float*)d_in[19];
    const float* Wf2 = (const float*)d_in[20];
    const float* bf2 = (const float*)d_in[21];
    float* out = (float*)d_out;

    float *qn, *oa, *q, *boa;
    __nv_bfloat16 *qa, *vr, *v, *samp, *q2, *hid, *wt;
    cudaGetSymbolAddress((void**)&qn,   g_qn);
    cudaGetSymbolAddress((void**)&qa,   g_qa);
    cudaGetSymbolAddress((void**)&oa,   g_oa);
    cudaGetSymbolAddress((void**)&vr,   g_vr);
    cudaGetSymbolAddress((void**)&v,    g_v);
    cudaGetSymbolAddress((void**)&samp, g_samp);
    cudaGetSymbolAddress((void**)&q,    g_q);
    cudaGetSymbolAddress((void**)&q2,   g_q2);
    cudaGetSymbolAddress((void**)&hid,  g_hid);
    cudaGetSymbolAddress((void**)&wt,   g_WT);
    cudaGetSymbolAddress((void**)&boa,  g_boa);

    cudaFuncSetAttribute(gemm_bf16, cudaFuncAttributeMaxDynamicSharedMemorySize, SM_BYTES);

    // 0. transpose + bf16-round weights; round value; concat bias
    transpose_all<<<dim3(32, 32, 6), dim3(32, 8)>>>(Wo, Wa, Wv, Wp, Wf1, Wf2, wt);
    round_kernel<<<(MV * EMBED + 255) / 256, 256>>>(value, vr, MV * EMBED, bo, ba, boa);

    // 1. qn = LN1(query) fp32; qa = bf16(qn + query_pos)
    ln_kernel<<<2048, 256>>>(query, g1, b1, qpos, qn, qa);

    // 2. fused offsets + logits GEMM (N=288)
    gemm_bf16<<<dim3(3, 128), 128, SM_BYTES>>>(qa, wt + WT_OA, boa, nullptr, nullptr,
                                               oa, nullptr, BQ, 288, 256, 0);

    // 3. value projection -> bf16
    gemm_bf16<<<dim3(2, 99), 128, SM_BYTES>>>(vr, wt + WT_V, bv, nullptr, nullptr,
                                              nullptr, v, MV, 256, 256, 0);

    // 4. deformable sampling (fused softmax), bf16 in/out
    sample_kernel<<<(BQ * HEADS * 32) / 256, 256>>>(v, oa, refp, samp);

    // 5. q = samp @ Wp + bp + qn + query
    gemm_bf16<<<dim3(2, 128), 128, SM_BYTES>>>(samp, wt + WT_P, bp, qn, query,
                                               q, nullptr, BQ, 256, 256, 0);

    // 6. q2 = bf16(LN2(q))
    ln_kernel<<<2048, 256>>>(q, g2, b2, nullptr, nullptr, q2);

    // 7. hid = bf16(gelu(q2 @ Wf1 + bf1))
    gemm_bf16<<<dim3(8, 128), 128, SM_BYTES>>>(q2, wt + WT_F1, bf1, nullptr, nullptr,
                                               nullptr, hid, BQ, 1024, 256, 1);

    // 8. out = q + hid @ Wf2 + bf2
    gemm_bf16<<<dim3(2, 128), 128, SM_BYTES>>>(hid, wt + WT_F2, bf2, q, nullptr,
                                               out, nullptr, BQ, 256, 1024, 0);
}

// round 13
// speedup vs baseline: 1.1623x; 1.1623x over previous
#include <cuda_runtime.h>
#include <cuda_bf16.h>
#include <math.h>
#include <stdint.h>

// ---------------------------------------------------------------------------
// Problem constants
// ---------------------------------------------------------------------------
#define BATCH   2
#define NQ      8192
#define EMBED   256
#define HEADS   8
#define DH      32
#define LEVELS  3
#define POINTS  4
#define NV      6300
#define BQ      (BATCH * NQ)   // 16384
#define MV      (BATCH * NV)   // 12600

// ---------------------------------------------------------------------------
// Scratch (device globals)
// ---------------------------------------------------------------------------
__device__ float          g_qn  [BQ * EMBED];   // LN1(query), fp32
__device__ __nv_bfloat16  g_qa  [BQ * EMBED];   // bf16(qn + query_pos)
__device__ float          g_oa  [BQ * 288];     // [offsets(192) | logits(96)] per row
__device__ __nv_bfloat16  g_vr  [MV * EMBED];   // bf16(value)
__device__ __nv_bfloat16  g_v   [MV * EMBED];   // bf16(value @ Wv + bv)
__device__ __nv_bfloat16  g_samp[BQ * EMBED];   // bf16 sampled output
__device__ float          g_q   [BQ * EMBED];
__device__ __nv_bfloat16  g_q2  [BQ * EMBED];   // bf16(LN2(q))
__device__ __nv_bfloat16  g_hid [BQ * 1024];    // bf16(gelu(...))
__device__ __nv_bfloat16  g_WT  [729088];       // transposed weights [N][K], bf16

#define WT_OA  0        // 288 x 256  (Wo^T rows 0..191, Wa^T rows 192..287)
#define WT_V   73728    // 256 x 256
#define WT_P   139264   // 256 x 256
#define WT_F1  204800   // 1024 x 256
#define WT_F2  466944   // 256 x 1024

// ---------------------------------------------------------------------------
// Helpers
// ---------------------------------------------------------------------------
__device__ __forceinline__ uint32_t smem_u32(const void* p) {
    uint32_t a;
    asm("{ .reg .u64 t; cvta.to.shared.u64 t, %1; cvt.u32.u64 %0, t; }"
        : "=r"(a) : "l"(p));
    return a;
}
#define CP_ASYNC16(dst, src, sz) \
    asm volatile("cp.async.cg.shared.global [%0], [%1], 16, %2;" \
                 :: "r"(dst), "l"(src), "r"(sz) : "memory")
#define CP_COMMIT() asm volatile("cp.async.commit_group;" ::: "memory")
#define CP_WAIT1()  asm volatile("cp.async.wait_group 1;" ::: "memory")
#define CP_WAIT0()  asm volatile("cp.async.wait_group 0;" ::: "memory")

#define LDSM_X4(r0, r1, r2, r3, addr) \
    asm volatile("ldmatrix.sync.aligned.m8n8.x4.shared.b16 {%0,%1,%2,%3}, [%4];" \
                 : "=r"(r0), "=r"(r1), "=r"(r2), "=r"(r3) : "r"(addr))

__device__ __forceinline__ void mma_bf16(float* c, const uint32_t* a, const uint32_t* b) {
    asm volatile(
        "mma.sync.aligned.m16n8k16.row.col.f32.bf16.bf16.f32 "
        "{%0,%1,%2,%3}, {%4,%5,%6,%7}, {%8,%9}, {%0,%1,%2,%3};"
        : "+f"(c[0]), "+f"(c[1]), "+f"(c[2]), "+f"(c[3])
        : "r"(a[0]), "r"(a[1]), "r"(a[2]), "r"(a[3]), "r"(b[0]), "r"(b[1]));
}

// ---------------------------------------------------------------------------
// Weight transpose + bf16 round: WT[n][k] = bf16(W[k][n])
// ---------------------------------------------------------------------------
__global__ void transpose_all(const float* __restrict__ W0, const float* __restrict__ W1,
                              const float* __restrict__ W2, const float* __restrict__ W3,
                              const float* __restrict__ W4, const float* __restrict__ W5,
                              __nv_bfloat16* __restrict__ WT)
{
    __shared__ float t[32][33];
    const int seg = blockIdx.z;
    const int Ks[6]  = {256, 256, 256, 256, 256, 1024};
    const int Ns[6]  = {192,  96, 256, 256, 1024, 256};
    const int Off[6] = {WT_OA, WT_OA + 192 * 256, WT_V, WT_P, WT_F1, WT_F2};
    const float* src = seg == 0 ? W0 : seg == 1 ? W1 : seg == 2 ? W2 :
                       seg == 3 ? W3 : seg == 4 ? W4 : W5;
    const int K = Ks[seg], N = Ns[seg];
    __nv_bfloat16* dst = WT + Off[seg];

    int bx = blockIdx.x * 32;
    int by = blockIdx.y * 32;
    if (bx >= N || by >= K) return;

    int x = bx + threadIdx.x;
#pragma unroll
    for (int j = 0; j < 32; j += 8) {
        int y = by + threadIdx.y + j;
        if (x < N && y < K) t[threadIdx.y + j][threadIdx.x] = src[(size_t)y * N + x];
    }
    __syncthreads();
    x = by + threadIdx.x;
#pragma unroll
    for (int j = 0; j < 32; j += 8) {
        int y = bx + threadIdx.y + j;
        if (x < K && y < N)
            dst[(size_t)y * K + x] = __float2bfloat16_rn(t[threadIdx.x][threadIdx.y + j]);
    }
}

// Round value input to bf16
__global__ void round_kernel(const float* __restrict__ src,
                             __nv_bfloat16* __restrict__ dst, int n)
{
    int i = blockIdx.x * blockDim.x + threadIdx.x;
    if (i < n) dst[i] = __float2bfloat16_rn(src[i]);
}

// ---------------------------------------------------------------------------
// bf16 HMMA GEMM (round-6 proven config).
// CTA = 256 threads, tile 128x128, 8 warps of 64x32, 3-stage cp.async, BK=32.
// bias2 (optional): bias for columns >= 192 (fused Wo|Wa bias split).
// ---------------------------------------------------------------------------
#define ABYTES   10240                  // 128 rows * 80B
#define STG      20480                  // A + B per stage
#define SM_BYTES (3 * STG)              // 61440

__global__ __launch_bounds__(256) void gemm_bf16(
    const __nv_bfloat16* __restrict__ A, const __nv_bfloat16* __restrict__ WT,
    const float* __restrict__ bias, const float* __restrict__ bias2,
    const float* __restrict__ add1, const float* __restrict__ add2,
    float* __restrict__ Cf, __nv_bfloat16* __restrict__ Cb,
    int M, int N, int K, int gelu_flag)
{
    extern __shared__ char smem[];
    const uint32_t sbase = smem_u32(smem);
    const int tid  = threadIdx.x;
    const int wid  = tid >> 5;
    const int lane = tid & 31;
    const int wm   = wid >> 2;
    const int wn   = wid & 3;
    const int m0   = blockIdx.y * 128;
    const int n0   = blockIdx.x * 128;

    float acc[4][4][4];
#pragma unroll
    for (int i = 0; i < 4; i++)
#pragma unroll
        for (int j = 0; j < 4; j++)
#pragma unroll
            for (int r = 0; r < 4; r++) acc[i][j][r] = 0.f;

    const int nk = K >> 5;

    auto load_tile = [&](int s, int kt) {
        const int k0 = kt * 32;
        const uint32_t base = sbase + (uint32_t)(s * STG);
#pragma unroll
        for (int t = 0; t < 2; t++) {
            int idx = tid + t * 256;
            int row = idx >> 2, c = idx & 3;
            int gm = m0 + row;
            int sz = (gm < M) ? 16 : 0;
            const __nv_bfloat16* src = A + (size_t)(sz ? gm : 0) * K + k0 + c * 8;
            CP_ASYNC16(base + (uint32_t)(row * 80 + c * 16), src, sz);
        }
#pragma unroll
        for (int t = 0; t < 2; t++) {
            int idx = tid + t * 256;
            int row = idx >> 2, c = idx & 3;
            int gn = n0 + row;
            int sz = (gn < N) ? 16 : 0;
            const __nv_bfloat16* src = WT + (size_t)(sz ? gn : 0) * K + k0 + c * 8;
            CP_ASYNC16(base + (uint32_t)(ABYTES + row * 80 + c * 16), src, sz);
        }
    };

    load_tile(0, 0); CP_COMMIT();
    load_tile(1, 1); CP_COMMIT();

    const int quad = lane >> 3;
    const int qr   = lane & 7;

    int s = 0;
    for (int kt = 0; kt < nk; kt++) {
        if (kt + 1 < nk) { CP_WAIT1(); } else { CP_WAIT0(); }
        __syncthreads();

        if (kt + 2 < nk) {
            load_tile((s + 2 >= 3) ? s - 1 : s + 2, kt + 2);
            CP_COMMIT();
        }

        const uint32_t abase = sbase + (uint32_t)(s * STG);
        const uint32_t bbase = abase + ABYTES;

#pragma unroll
        for (int ks = 0; ks < 2; ks++) {
            const int k0 = ks * 16;
            uint32_t a[4][4];
#pragma unroll
            for (int mi = 0; mi < 4; mi++) {
                int mrow = wm * 64 + mi * 16 + (quad & 1) * 8 + qr;
                uint32_t addr = abase + (uint32_t)(mrow * 80 + (k0 + (quad >> 1) * 8) * 2);
                LDSM_X4(a[mi][0], a[mi][1], a[mi][2], a[mi][3], addr);
            }
            uint32_t b[4][2];
#pragma unroll
            for (int nj = 0; nj < 2; nj++) {
                int nrow = wn * 32 + nj * 16 + ((quad >> 1) & 1) * 8 + qr;
                uint32_t addr = bbase + (uint32_t)(nrow * 80 + (k0 + (quad & 1) * 8) * 2);
                LDSM_X4(b[nj * 2][0], b[nj * 2][1], b[nj * 2 + 1][0], b[nj * 2 + 1][1], addr);
            }
#pragma unroll
            for (int mi = 0; mi < 4; mi++)
#pragma unroll
                for (int ni = 0; ni < 4; ni++)
                    mma_bf16(acc[mi][ni], a[mi], b[ni]);
        }
        s = (s + 1 >= 3) ? 0 : s + 1;
    }

    // ---- epilogue ----
    const int g = lane >> 2;
    const int c2 = lane & 3;
#pragma unroll
    for (int mi = 0; mi < 4; mi++) {
#pragma unroll
        for (int ni = 0; ni < 4; ni++) {
            int row = m0 + wm * 64 + mi * 16 + g;
            int col = n0 + wn * 32 + ni * 8 + c2 * 2;
            if (col >= N) continue;
            const float* bsrc = (bias2 && col >= 192) ? (bias2 + col - 192) : (bias + col);
            float2 bs = *(const float2*)bsrc;
#pragma unroll
            for (int half = 0; half < 2; half++) {
                int r = row + half * 8;
                if (r >= M) continue;
                size_t idx = (size_t)r * N + col;
                float vx = acc[mi][ni][half * 2 + 0] + bs.x;
                float vy = acc[mi][ni][half * 2 + 1] + bs.y;
                if (add1) {
                    float2 a1 = *(const float2*)&add1[idx];
                    vx += a1.x; vy += a1.y;
                }
                if (add2) {
                    float2 a2 = *(const float2*)&add2[idx];
                    vx += a2.x; vy += a2.y;
                }
                if (gelu_flag) {
                    vx = 0.5f * vx * (1.f + erff(vx * 0.70710678118654752f));
                    vy = 0.5f * vy * (1.f + erff(vy * 0.70710678118654752f));
                }
                if (Cf) {
                    float2 o; o.x = vx; o.y = vy;
                    *(float2*)&Cf[idx] = o;
                } else {
                    __nv_bfloat162 o;
                    o.x = __float2bfloat16_rn(vx);
                    o.y = __float2bfloat16_rn(vy);
                    *(__nv_bfloat162*)&Cb[idx] = o;
                }
            }
        }
    }
}

// ---------------------------------------------------------------------------
// LayerNorm: one warp per row of 256.
// ---------------------------------------------------------------------------
__global__ void ln_kernel(const float* __restrict__ x,
                          const float* __restrict__ gamma,
                          const float* __restrict__ beta,
                          const float* __restrict__ pos,
                          float* __restrict__ out_f,
                          __nv_bfloat16* __restrict__ out_b)
{
    int warp = (blockIdx.x * blockDim.x + threadIdx.x) >> 5;
    int lane = threadIdx.x & 31;
    if (warp >= BQ) return;

    const float* xr = x + (size_t)warp * EMBED;
    float v[8];
    float s = 0.f;
#pragma unroll
    for (int i = 0; i < 8; i++) { v[i] = xr[i * 32 + lane]; s += v[i]; }
#pragma unroll
    for (int o = 16; o > 0; o >>= 1) s += __shfl_xor_sync(0xFFFFFFFFu, s, o);
    float mean = s * (1.f / EMBED);

    float s2 = 0.f;
#pragma unroll
    for (int i = 0; i < 8; i++) { float d = v[i] - mean; s2 += d * d; }
#pragma unroll
    for (int o = 16; o > 0; o >>= 1) s2 += __shfl_xor_sync(0xFFFFFFFFu, s2, o);
    float rstd = rsqrtf(s2 * (1.f / EMBED) + 1e-5f);

    size_t base = (size_t)warp * EMBED;
#pragma unroll
    for (int i = 0; i < 8; i++) {
        int c = i * 32 + lane;
        float nv = (v[i] - mean) * rstd * gamma[c] + beta[c];
        if (out_f) out_f[base + c] = nv;
        if (out_b) {
            float ov = pos ? (nv + pos[base + c]) : nv;
            out_b[base + c] = __float2bfloat16_rn(ov);
        }
    }
}

// ---------------------------------------------------------------------------
// Deformable sampling, fused softmax, bf16 value, pair-of-points scheme.
// ---------------------------------------------------------------------------
__global__ void sample_kernel(const __nv_bfloat16* __restrict__ v,
                              const float* __restrict__ oa,
                              const float* __restrict__ ref,
                              __nv_bfloat16* __restrict__ out)
{
    const int LH[3] = {60, 30, 15};
    const int LW[3] = {80, 40, 20};
    const int LS[3] = {0, 4800, 6000};

    int warp = (blockIdx.x * blockDim.x + threadIdx.x) >> 5;
    int lane = threadIdx.x & 31;
    if (warp >= BQ * HEADS) return;

    int h  = warp & 7;
    int bq = warp >> 3;
    int b  = bq / NQ;

    const float* row  = oa + (size_t)bq * 288;
    const float* offr = row + h * 24;
    const float* lg   = row + 192 + h * 12;
    const float* refr = ref + (size_t)bq * (LEVELS * 2);

    float w[12];
    float mx = -1e30f;
#pragma unroll
    for (int i = 0; i < 12; i++) { w[i] = lg[i]; mx = fmaxf(mx, w[i]); }
    float ssum = 0.f;
#pragma unroll
    for (int i = 0; i < 12; i++) { w[i] = __expf(w[i] - mx); ssum += w[i]; }
    float inv = 1.f / ssum;

    const int gg = lane >> 4;
    const int li = lane & 15;

    float ax = 0.f, ay = 0.f;

#pragma unroll
    for (int j = 0; j < 6; j++) {
        const int l = j >> 1;
        const int p = 2 * (j & 1) + gg;
        const int Hl = LH[l], Wl = LW[l];

        float gx = refr[l * 2 + 0] * (float)Wl - 0.5f + offr[l * 8 + p * 2 + 0];
        float gy = refr[l * 2 + 1] * (float)Hl - 0.5f + offr[l * 8 + p * 2 + 1];
        float x0f = floorf(gx), y0f = floorf(gy);
        float wx = gx - x0f, wy = gy - y0f;
        int x0 = (int)x0f, y0 = (int)y0f;

        float w00 = (1.f - wx) * (1.f - wy);
        float w10 = wx * (1.f - wy);
        float w01 = (1.f - wx) * wy;
        float w11 = wx * wy;

        bool xv0 = (x0 >= 0) & (x0 < Wl);
        bool xv1 = (x0 + 1 >= 0) & (x0 + 1 < Wl);
        bool yv0 = (y0 >= 0) & (y0 < Hl);
        bool yv1 = (y0 + 1 >= 0) & (y0 + 1 < Hl);

        const __nv_bfloat16* vb = v + (((size_t)b * NV + LS[l]) * EMBED) + h * DH + 2 * li;

        float sx = 0.f, sy = 0.f;
        if (xv0 & yv0) {
            float2 c = __bfloat1622float2(*(const __nv_bfloat162*)(vb + (size_t)(y0 * Wl + x0) * EMBED));
            sx += w00 * c.x; sy += w00 * c.y;
        }
        if (xv1 & yv0) {
            float2 c = __bfloat1622float2(*(const __nv_bfloat162*)(vb + (size_t)(y0 * Wl + x0 + 1) * EMBED));
            sx += w10 * c.x; sy += w10 * c.y;
        }
        if (xv0 & yv1) {
            float2 c = __bfloat1622float2(*(const __nv_bfloat162*)(vb + (size_t)((y0 + 1) * Wl + x0) * EMBED));
            sx += w01 * c.x; sy += w01 * c.y;
        }
        if (xv1 & yv1) {
            float2 c = __bfloat1622float2(*(const __nv_bfloat162*)(vb + (size_t)((y0 + 1) * Wl + x0 + 1) * EMBED));
            sx += w11 * c.x; sy += w11 * c.y;
        }

        float wt = w[l * 4 + p] * inv;
        ax = fmaf(wt, sx, ax);
        ay = fmaf(wt, sy, ay);
    }

    ax += __shfl_xor_sync(0xFFFFFFFFu, ax, 16);
    ay += __shfl_xor_sync(0xFFFFFFFFu, ay, 16);

    if (gg == 0) {
        __nv_bfloat162 o;
        o.x = __float2bfloat16_rn(ax);
        o.y = __float2bfloat16_rn(ay);
        *(__nv_bfloat162*)&out[(size_t)bq * EMBED + h * DH + 2 * li] = o;
    }
}

// ---------------------------------------------------------------------------
// Launch (multi-stream fork for the independent V chain)
// ---------------------------------------------------------------------------
extern "C" void kernel_launch(void* const* d_in, const int* in_sizes, int n_in,
                              void* d_out, int out_size)
{
    (void)in_sizes; (void)n_in; (void)out_size;

    const float* query = (const float*)d_in[0];
    const float* value = (const float*)d_in[1];
    const float* qpos  = (const float*)d_in[2];
    const float* refp  = (const float*)d_in[3];
    const float* g1  = (const float*)d_in[6];
    const float* b1  = (const float*)d_in[7];
    const float* Wo  = (const float*)d_in[8];
    const float* bo  = (const float*)d_in[9];
    const float* Wa  = (const float*)d_in[10];
    const float* ba  = (const float*)d_in[11];
    const float* Wv  = (const float*)d_in[12];
    const float* bv  = (const float*)d_in[13];
    const float* Wp  = (const float*)d_in[14];
    const float* bp  = (const float*)d_in[15];
    const float* g2  = (const float*)d_in[16];
    const float* b2  = (const float*)d_in[17];
    const float* Wf1 = (const float*)d_in[18];
    const float* bf1 = (const float*)d_in[19];
    const float* Wf2 = (const float*)d_in[20];
    const float* bf2 = (const float*)d_in[21];
    float* out = (float*)d_out;

    float *qn, *oa, *q;
    __nv_bfloat16 *qa, *vr, *v, *samp, *q2, *hid, *wt;
    cudaGetSymbolAddress((void**)&qn,   g_qn);
    cudaGetSymbolAddress((void**)&qa,   g_qa);
    cudaGetSymbolAddress((void**)&oa,   g_oa);
    cudaGetSymbolAddress((void**)&vr,   g_vr);
    cudaGetSymbolAddress((void**)&v,    g_v);
    cudaGetSymbolAddress((void**)&samp, g_samp);
    cudaGetSymbolAddress((void**)&q,    g_q);
    cudaGetSymbolAddress((void**)&q2,   g_q2);
    cudaGetSymbolAddress((void**)&hid,  g_hid);
    cudaGetSymbolAddress((void**)&wt,   g_WT);

    cudaFuncSetAttribute(gemm_bf16, cudaFuncAttributeMaxDynamicSharedMemorySize, SM_BYTES);

    // One-time stream/event setup (first call = correctness run, not captured).
    static cudaStream_t s1 = nullptr;
    static cudaEvent_t ev0 = nullptr, evT = nullptr, evV = nullptr;
    if (!s1) {
        cudaStreamCreateWithFlags(&s1, cudaStreamNonBlocking);
        cudaEventCreateWithFlags(&ev0, cudaEventDisableTiming);
        cudaEventCreateWithFlags(&evT, cudaEventDisableTiming);
        cudaEventCreateWithFlags(&evV, cudaEventDisableTiming);
    }

    // Fork s1 from the main (capture-origin) stream.
    cudaEventRecord(ev0, 0);
    cudaStreamWaitEvent(s1, ev0, 0);

    // s1: value -> bf16 (independent of weights)
    round_kernel<<<(MV * EMBED + 255) / 256, 256, 0, s1>>>(value, vr, MV * EMBED);

    // main: weight transpose, then signal s1
    transpose_all<<<dim3(32, 32, 6), dim3(32, 8)>>>(Wo, Wa, Wv, Wp, Wf1, Wf2, wt);
    cudaEventRecord(evT, 0);
    cudaStreamWaitEvent(s1, evT, 0);

    // s1: value projection -> bf16
    gemm_bf16<<<dim3(2, 99), 256, SM_BYTES, s1>>>(vr, wt + WT_V, bv, nullptr,
                                                  nullptr, nullptr, nullptr, v,
                                                  MV, 256, 256, 0);
    cudaEventRecord(evV, s1);

    // main: LN1 then fused offsets+logits GEMM (overlaps with s1)
    ln_kernel<<<2048, 256>>>(query, g1, b1, qpos, qn, qa);
    gemm_bf16<<<dim3(3, 128), 256, SM_BYTES>>>(qa, wt + WT_OA, bo, ba, nullptr,
                                               nullptr, oa, nullptr, BQ, 288, 256, 0);

    // join: sampling needs v (s1) and oa (main)
    cudaStreamWaitEvent(0, evV, 0);
    sample_kernel<<<(BQ * HEADS * 32) / 256, 256>>>(v, oa, refp, samp);

    // q = samp @ Wp + bp + qn + query
    gemm_bf16<<<dim3(2, 128), 256, SM_BYTES>>>(samp, wt + WT_P, bp, nullptr, qn, query,
                                               q, nullptr, BQ, 256, 256, 0);

    // q2 = bf16(LN2(q))
    ln_kernel<<<2048, 256>>>(q, g2, b2, nullptr, nullptr, q2);

    // hid = bf16(gelu(q2 @ Wf1 + bf1))
    gemm_bf16<<<dim3(8, 128), 256, SM_BYTES>>>(q2, wt + WT_F1, bf1, nullptr, nullptr,
                                               nullptr, nullptr, hid, BQ, 1024, 256, 1);

    // out = q + hid @ Wf2 + bf2
    gemm_bf16<<<dim3(2, 128), 256, SM_BYTES>>>(hid, wt + WT_F2, bf2, nullptr, q, nullptr,
                                               out, nullptr, BQ, 256, 1024, 0);
}

// round 14
// speedup vs baseline: 1.2428x; 1.0693x over previous
#include <cuda_runtime.h>
#include <cuda_bf16.h>
#include <math.h>
#include <stdint.h>

// ---------------------------------------------------------------------------
// Problem constants
// ---------------------------------------------------------------------------
#define BATCH   2
#define NQ      8192
#define EMBED   256
#define HEADS   8
#define DH      32
#define LEVELS  3
#define POINTS  4
#define NV      6300
#define BQ      (BATCH * NQ)   // 16384
#define MV      (BATCH * NV)   // 12600

// ---------------------------------------------------------------------------
// Scratch (device globals)
// ---------------------------------------------------------------------------
__device__ float          g_qn  [BQ * EMBED];   // LN1(query), fp32
__device__ __nv_bfloat16  g_qa  [BQ * EMBED];   // bf16(qn + query_pos)
__device__ float          g_oa  [BQ * 288];     // [offsets(192) | logits(96)] per row
__device__ __nv_bfloat16  g_vr  [MV * EMBED];   // bf16(value)
__device__ __nv_bfloat16  g_v   [MV * EMBED];   // bf16(value @ Wv + bv)
__device__ __nv_bfloat16  g_samp[BQ * EMBED];   // bf16 sampled output
__device__ float          g_q   [BQ * EMBED];
__device__ __nv_bfloat16  g_q2  [BQ * EMBED];   // bf16(LN2(q))
__device__ __nv_bfloat16  g_hid [BQ * 1024];    // bf16(gelu(...))
__device__ __nv_bfloat16  g_WT  [729088];       // transposed weights [N][K], bf16

#define WT_OA  0        // 288 x 256  (Wo^T rows 0..191, Wa^T rows 192..287)
#define WT_V   73728    // 256 x 256
#define WT_P   139264   // 256 x 256
#define WT_F1  204800   // 1024 x 256
#define WT_F2  466944   // 256 x 1024

// ---------------------------------------------------------------------------
// Helpers
// ---------------------------------------------------------------------------
__device__ __forceinline__ uint32_t smem_u32(const void* p) {
    uint32_t a;
    asm("{ .reg .u64 t; cvta.to.shared.u64 t, %1; cvt.u32.u64 %0, t; }"
        : "=r"(a) : "l"(p));
    return a;
}
#define CP_ASYNC16(dst, src, sz) \
    asm volatile("cp.async.cg.shared.global [%0], [%1], 16, %2;" \
                 :: "r"(dst), "l"(src), "r"(sz) : "memory")
#define CP_COMMIT() asm volatile("cp.async.commit_group;" ::: "memory")
#define CP_WAIT2()  asm volatile("cp.async.wait_group 2;" ::: "memory")
#define CP_WAIT1()  asm volatile("cp.async.wait_group 1;" ::: "memory")
#define CP_WAIT0()  asm volatile("cp.async.wait_group 0;" ::: "memory")

#define LDSM_X4(r0, r1, r2, r3, addr) \
    asm volatile("ldmatrix.sync.aligned.m8n8.x4.shared.b16 {%0,%1,%2,%3}, [%4];" \
                 : "=r"(r0), "=r"(r1), "=r"(r2), "=r"(r3) : "r"(addr))

__device__ __forceinline__ void mma_bf16(float* c, const uint32_t* a, const uint32_t* b) {
    asm volatile(
        "mma.sync.aligned.m16n8k16.row.col.f32.bf16.bf16.f32 "
        "{%0,%1,%2,%3}, {%4,%5,%6,%7}, {%8,%9}, {%0,%1,%2,%3};"
        : "+f"(c[0]), "+f"(c[1]), "+f"(c[2]), "+f"(c[3])
        : "r"(a[0]), "r"(a[1]), "r"(a[2]), "r"(a[3]), "r"(b[0]), "r"(b[1]));
}

// ---------------------------------------------------------------------------
// Weight transpose + bf16 round: WT[n][k] = bf16(W[k][n])
// ---------------------------------------------------------------------------
__global__ void transpose_all(const float* __restrict__ W0, const float* __restrict__ W1,
                              const float* __restrict__ W2, const float* __restrict__ W3,
                              const float* __restrict__ W4, const float* __restrict__ W5,
                              __nv_bfloat16* __restrict__ WT)
{
    __shared__ float t[32][33];
    const int seg = blockIdx.z;
    const int Ks[6]  = {256, 256, 256, 256, 256, 1024};
    const int Ns[6]  = {192,  96, 256, 256, 1024, 256};
    const int Off[6] = {WT_OA, WT_OA + 192 * 256, WT_V, WT_P, WT_F1, WT_F2};
    const float* src = seg == 0 ? W0 : seg == 1 ? W1 : seg == 2 ? W2 :
                       seg == 3 ? W3 : seg == 4 ? W4 : W5;
    const int K = Ks[seg], N = Ns[seg];
    __nv_bfloat16* dst = WT + Off[seg];

    int bx = blockIdx.x * 32;
    int by = blockIdx.y * 32;
    if (bx >= N || by >= K) return;

    int x = bx + threadIdx.x;
#pragma unroll
    for (int j = 0; j < 32; j += 8) {
        int y = by + threadIdx.y + j;
        if (x < N && y < K) t[threadIdx.y + j][threadIdx.x] = src[(size_t)y * N + x];
    }
    __syncthreads();
    x = by + threadIdx.x;
#pragma unroll
    for (int j = 0; j < 32; j += 8) {
        int y = bx + threadIdx.y + j;
        if (x < K && y < N)
            dst[(size_t)y * K + x] = __float2bfloat16_rn(t[threadIdx.x][threadIdx.y + j]);
    }
}

// Round value input to bf16
__global__ void round_kernel(const float* __restrict__ src,
                             __nv_bfloat16* __restrict__ dst, int n)
{
    int i = blockIdx.x * blockDim.x + threadIdx.x;
    if (i < n) dst[i] = __float2bfloat16_rn(src[i]);
}

// ---------------------------------------------------------------------------
// bf16 HMMA GEMM, persistent grid-stride over 128x128 tiles.
// CTA = 256 threads, 8 warps of 64x32, 4-stage cp.async pipeline, BK=32.
// bias2 (optional): bias for columns >= 192 (fused Wo|Wa bias split).
// ---------------------------------------------------------------------------
#define ABYTES   10240                  // 128 rows * 80B
#define STG      20480                  // A + B per stage
#define SM_BYTES (4 * STG)              // 81920

__global__ __launch_bounds__(256) void gemm_bf16(
    const __nv_bfloat16* __restrict__ A, const __nv_bfloat16* __restrict__ WT,
    const float* __restrict__ bias, const float* __restrict__ bias2,
    const float* __restrict__ add1, const float* __restrict__ add2,
    float* __restrict__ Cf, __nv_bfloat16* __restrict__ Cb,
    int M, int N, int K, int gelu_flag)
{
    extern __shared__ char smem[];
    const uint32_t sbase = smem_u32(smem);
    const int tid  = threadIdx.x;
    const int wid  = tid >> 5;
    const int lane = tid & 31;
    const int wm   = wid >> 2;
    const int wn   = wid & 3;
    const int quad = lane >> 3;
    const int qr   = lane & 7;
    const int g    = lane >> 2;
    const int c2   = lane & 3;

    const int ntx = (N + 127) >> 7;
    const int nty = (M + 127) >> 7;
    const int ntiles = ntx * nty;
    const int nk = K >> 5;

    for (int t = blockIdx.x; t < ntiles; t += gridDim.x) {
        const int m0 = (t / ntx) * 128;
        const int n0 = (t % ntx) * 128;

        float acc[4][4][4];
#pragma unroll
        for (int i = 0; i < 4; i++)
#pragma unroll
            for (int j = 0; j < 4; j++)
#pragma unroll
                for (int r = 0; r < 4; r++) acc[i][j][r] = 0.f;

        auto load_tile = [&](int s, int kt) {
            const int k0 = kt * 32;
            const uint32_t base = sbase + (uint32_t)(s * STG);
#pragma unroll
            for (int u = 0; u < 2; u++) {
                int idx = tid + u * 256;
                int row = idx >> 2, c = idx & 3;
                int gm = m0 + row;
                int sz = (gm < M) ? 16 : 0;
                const __nv_bfloat16* src = A + (size_t)(sz ? gm : 0) * K + k0 + c * 8;
                CP_ASYNC16(base + (uint32_t)(row * 80 + c * 16), src, sz);
            }
#pragma unroll
            for (int u = 0; u < 2; u++) {
                int idx = tid + u * 256;
                int row = idx >> 2, c = idx & 3;
                int gn = n0 + row;
                int sz = (gn < N) ? 16 : 0;
                const __nv_bfloat16* src = WT + (size_t)(sz ? gn : 0) * K + k0 + c * 8;
                CP_ASYNC16(base + (uint32_t)(ABYTES + row * 80 + c * 16), src, sz);
            }
        };

        load_tile(0, 0); CP_COMMIT();
        load_tile(1, 1); CP_COMMIT();
        load_tile(2, 2); CP_COMMIT();

        for (int kt = 0; kt < nk; kt++) {
            if (kt < nk - 2)      { CP_WAIT2(); }
            else if (kt == nk - 2){ CP_WAIT1(); }
            else                  { CP_WAIT0(); }
            __syncthreads();

            if (kt + 3 < nk) {
                load_tile((kt + 3) & 3, kt + 3);
                CP_COMMIT();
            }

            const uint32_t abase = sbase + (uint32_t)((kt & 3) * STG);
            const uint32_t bbase = abase + ABYTES;

#pragma unroll
            for (int ks = 0; ks < 2; ks++) {
                const int k0 = ks * 16;
                uint32_t a[4][4];
#pragma unroll
                for (int mi = 0; mi < 4; mi++) {
                    int mrow = wm * 64 + mi * 16 + (quad & 1) * 8 + qr;
                    uint32_t addr = abase + (uint32_t)(mrow * 80 + (k0 + (quad >> 1) * 8) * 2);
                    LDSM_X4(a[mi][0], a[mi][1], a[mi][2], a[mi][3], addr);
                }
                uint32_t b[4][2];
#pragma unroll
                for (int nj = 0; nj < 2; nj++) {
                    int nrow = wn * 32 + nj * 16 + ((quad >> 1) & 1) * 8 + qr;
                    uint32_t addr = bbase + (uint32_t)(nrow * 80 + (k0 + (quad & 1) * 8) * 2);
                    LDSM_X4(b[nj * 2][0], b[nj * 2][1], b[nj * 2 + 1][0], b[nj * 2 + 1][1], addr);
                }
#pragma unroll
                for (int mi = 0; mi < 4; mi++)
#pragma unroll
                    for (int ni = 0; ni < 4; ni++)
                        mma_bf16(acc[mi][ni], a[mi], b[ni]);
            }
        }

        // ---- epilogue ----
#pragma unroll
        for (int mi = 0; mi < 4; mi++) {
#pragma unroll
            for (int ni = 0; ni < 4; ni++) {
                int row = m0 + wm * 64 + mi * 16 + g;
                int col = n0 + wn * 32 + ni * 8 + c2 * 2;
                if (col >= N) continue;
                const float* bsrc = (bias2 && col >= 192) ? (bias2 + col - 192) : (bias + col);
                float2 bs = *(const float2*)bsrc;
#pragma unroll
                for (int half = 0; half < 2; half++) {
                    int r = row + half * 8;
                    if (r >= M) continue;
                    size_t idx = (size_t)r * N + col;
                    float vx = acc[mi][ni][half * 2 + 0] + bs.x;
                    float vy = acc[mi][ni][half * 2 + 1] + bs.y;
                    if (add1) {
                        float2 a1 = *(const float2*)&add1[idx];
                        vx += a1.x; vy += a1.y;
                    }
                    if (add2) {
                        float2 a2 = *(const float2*)&add2[idx];
                        vx += a2.x; vy += a2.y;
                    }
                    if (gelu_flag) {
                        vx = 0.5f * vx * (1.f + erff(vx * 0.70710678118654752f));
                        vy = 0.5f * vy * (1.f + erff(vy * 0.70710678118654752f));
                    }
                    if (Cf) {
                        float2 o; o.x = vx; o.y = vy;
                        *(float2*)&Cf[idx] = o;
                    } else {
                        __nv_bfloat162 o;
                        o.x = __float2bfloat16_rn(vx);
                        o.y = __float2bfloat16_rn(vy);
                        *(__nv_bfloat162*)&Cb[idx] = o;
                    }
                }
            }
        }
        __syncthreads();
    }
}

// ---------------------------------------------------------------------------
// LayerNorm: one warp per row of 256.
// ---------------------------------------------------------------------------
__global__ void ln_kernel(const float* __restrict__ x,
                          const float* __restrict__ gamma,
                          const float* __restrict__ beta,
                          const float* __restrict__ pos,
                          float* __restrict__ out_f,
                          __nv_bfloat16* __restrict__ out_b)
{
    int warp = (blockIdx.x * blockDim.x + threadIdx.x) >> 5;
    int lane = threadIdx.x & 31;
    if (warp >= BQ) return;

    const float* xr = x + (size_t)warp * EMBED;
    float v[8];
    float s = 0.f;
#pragma unroll
    for (int i = 0; i < 8; i++) { v[i] = xr[i * 32 + lane]; s += v[i]; }
#pragma unroll
    for (int o = 16; o > 0; o >>= 1) s += __shfl_xor_sync(0xFFFFFFFFu, s, o);
    float mean = s * (1.f / EMBED);

    float s2 = 0.f;
#pragma unroll
    for (int i = 0; i < 8; i++) { float d = v[i] - mean; s2 += d * d; }
#pragma unroll
    for (int o = 16; o > 0; o >>= 1) s2 += __shfl_xor_sync(0xFFFFFFFFu, s2, o);
    float rstd = rsqrtf(s2 * (1.f / EMBED) + 1e-5f);

    size_t base = (size_t)warp * EMBED;
#pragma unroll
    for (int i = 0; i < 8; i++) {
        int c = i * 32 + lane;
        float nv = (v[i] - mean) * rstd * gamma[c] + beta[c];
        if (out_f) out_f[base + c] = nv;
        if (out_b) {
            float ov = pos ? (nv + pos[base + c]) : nv;
            out_b[base + c] = __float2bfloat16_rn(ov);
        }
    }
}

// ---------------------------------------------------------------------------
// Deformable sampling, fused softmax, bf16 value.
// One warp per (b,q,h). 4 lane-groups of 8; group gg handles point gg of
// each level; each lane covers 4 channels via one 8B load per corner.
// Two-level shfl reduce across groups.
// ---------------------------------------------------------------------------
__global__ void sample_kernel(const __nv_bfloat16* __restrict__ v,
                              const float* __restrict__ oa,
                              const float* __restrict__ ref,
                              __nv_bfloat16* __restrict__ out)
{
    const int LH[3] = {60, 30, 15};
    const int LW[3] = {80, 40, 20};
    const int LS[3] = {0, 4800, 6000};

    int warp = (blockIdx.x * blockDim.x + threadIdx.x) >> 5;
    int lane = threadIdx.x & 31;
    if (warp >= BQ * HEADS) return;

    int h  = warp & 7;
    int bq = warp >> 3;
    int b  = bq / NQ;

    const float* row  = oa + (size_t)bq * 288;
    const float* offr = row + h * 24;
    const float* lg   = row + 192 + h * 12;
    const float* refr = ref + (size_t)bq * (LEVELS * 2);

    float w[12];
    float mx = -1e30f;
#pragma unroll
    for (int i = 0; i < 12; i++) { w[i] = lg[i]; mx = fmaxf(mx, w[i]); }
    float ssum = 0.f;
#pragma unroll
    for (int i = 0; i < 12; i++) { w[i] = __expf(w[i] - mx); ssum += w[i]; }
    float inv = 1.f / ssum;

    const int gg = lane >> 3;       // point index within each level
    const int li = lane & 7;        // 4-channel group index

    float a0 = 0.f, a1 = 0.f, a2 = 0.f, a3 = 0.f;

#pragma unroll
    for (int l = 0; l < LEVELS; l++) {
        const int Hl = LH[l], Wl = LW[l];
        const int p = gg;

        float gx = refr[l * 2 + 0] * (float)Wl - 0.5f + offr[l * 8 + p * 2 + 0];
        float gy = refr[l * 2 + 1] * (float)Hl - 0.5f + offr[l * 8 + p * 2 + 1];
        float x0f = floorf(gx), y0f = floorf(gy);
        float wx = gx - x0f, wy = gy - y0f;
        int x0 = (int)x0f, y0 = (int)y0f;

        float w00 = (1.f - wx) * (1.f - wy);
        float w10 = wx * (1.f - wy);
        float w01 = (1.f - wx) * wy;
        float w11 = wx * wy;

        bool xv0 = (x0 >= 0) & (x0 < Wl);
        bool xv1 = (x0 + 1 >= 0) & (x0 + 1 < Wl);
        bool yv0 = (y0 >= 0) & (y0 < Hl);
        bool yv1 = (y0 + 1 >= 0) & (y0 + 1 < Hl);

        const __nv_bfloat16* vb = v + (((size_t)b * NV + LS[l]) * EMBED) + h * DH + 4 * li;

        float s0 = 0.f, s1 = 0.f, s2 = 0.f, s3 = 0.f;
#define CORNER(cond, wgt, off)                                                       \
        if (cond) {                                                                  \
            uint2 u = *(const uint2*)(vb + (size_t)(off) * EMBED);                   \
            float2 clo = __bfloat1622float2(*(__nv_bfloat162*)&u.x);                 \
            float2 chi = __bfloat1622float2(*(__nv_bfloat162*)&u.y);                 \
            s0 += (wgt) * clo.x; s1 += (wgt) * clo.y;                                \
            s2 += (wgt) * chi.x; s3 += (wgt) * chi.y;                                \
        }
        CORNER(xv0 & yv0, w00, y0 * Wl + x0)
        CORNER(xv1 & yv0, w10, y0 * Wl + x0 + 1)
        CORNER(xv0 & yv1, w01, (y0 + 1) * Wl + x0)
        CORNER(xv1 & yv1, w11, (y0 + 1) * Wl + x0 + 1)
#undef CORNER

        float wt = w[l * 4 + p] * inv;
        a0 = fmaf(wt, s0, a0);
        a1 = fmaf(wt, s1, a1);
        a2 = fmaf(wt, s2, a2);
        a3 = fmaf(wt, s3, a3);
    }

    // combine the four point-groups (channels identical across groups)
#pragma unroll
    for (int o = 8; o <= 16; o <<= 1) {
        a0 += __shfl_xor_sync(0xFFFFFFFFu, a0, o);
        a1 += __shfl_xor_sync(0xFFFFFFFFu, a1, o);
        a2 += __shfl_xor_sync(0xFFFFFFFFu, a2, o);
        a3 += __shfl_xor_sync(0xFFFFFFFFu, a3, o);
    }

    if (gg == 0) {
        __nv_bfloat162 lo, hi;
        lo.x = __float2bfloat16_rn(a0); lo.y = __float2bfloat16_rn(a1);
        hi.x = __float2bfloat16_rn(a2); hi.y = __float2bfloat16_rn(a3);
        uint2 u;
        u.x = *(uint32_t*)&lo; u.y = *(uint32_t*)&hi;
        *(uint2*)&out[(size_t)bq * EMBED + h * DH + 4 * li] = u;
    }
}

// ---------------------------------------------------------------------------
// Launch (multi-stream fork for the independent V chain)
// ---------------------------------------------------------------------------
extern "C" void kernel_launch(void* const* d_in, const int* in_sizes, int n_in,
                              void* d_out, int out_size)
{
    (void)in_sizes; (void)n_in; (void)out_size;

    const float* query = (const float*)d_in[0];
    const float* value = (const float*)d_in[1];
    const float* qpos  = (const float*)d_in[2];
    const float* refp  = (const float*)d_in[3];
    const float* g1  = (const float*)d_in[6];
    const float* b1  = (const float*)d_in[7];
    const float* Wo  = (const float*)d_in[8];
    const float* bo  = (const float*)d_in[9];
    const float* Wa  = (const float*)d_in[10];
    const float* ba  = (const float*)d_in[11];
    const float* Wv  = (const float*)d_in[12];
    const float* bv  = (const float*)d_in[13];
    const float* Wp  = (const float*)d_in[14];
    const float* bp  = (const float*)d_in[15];
    const float* g2  = (const float*)d_in[16];
    const float* b2  = (const float*)d_in[17];
    const float* Wf1 = (const float*)d_in[18];
    const float* bf1 = (const float*)d_in[19];
    const float* Wf2 = (const float*)d_in[20];
    const float* bf2 = (const float*)d_in[21];
    float* out = (float*)d_out;

    float *qn, *oa, *q;
    __nv_bfloat16 *qa, *vr, *v, *samp, *q2, *hid, *wt;
    cudaGetSymbolAddress((void**)&qn,   g_qn);
    cudaGetSymbolAddress((void**)&qa,   g_qa);
    cudaGetSymbolAddress((void**)&oa,   g_oa);
    cudaGetSymbolAddress((void**)&vr,   g_vr);
    cudaGetSymbolAddress((void**)&v,    g_v);
    cudaGetSymbolAddress((void**)&samp, g_samp);
    cudaGetSymbolAddress((void**)&q,    g_q);
    cudaGetSymbolAddress((void**)&q2,   g_q2);
    cudaGetSymbolAddress((void**)&hid,  g_hid);
    cudaGetSymbolAddress((void**)&wt,   g_WT);

    cudaFuncSetAttribute(gemm_bf16, cudaFuncAttributeMaxDynamicSharedMemorySize, SM_BYTES);

    static cudaStream_t s1 = nullptr;
    static cudaEvent_t ev0 = nullptr, evT = nullptr, evV = nullptr;
    if (!s1) {
        cudaStreamCreateWithFlags(&s1, cudaStreamNonBlocking);
        cudaEventCreateWithFlags(&ev0, cudaEventDisableTiming);
        cudaEventCreateWithFlags(&evT, cudaEventDisableTiming);
        cudaEventCreateWithFlags(&evV, cudaEventDisableTiming);
    }

    // Fork s1 from the main stream.
    cudaEventRecord(ev0, 0);
    cudaStreamWaitEvent(s1, ev0, 0);

    // s1: value -> bf16
    round_kernel<<<(MV * EMBED + 255) / 256, 256, 0, s1>>>(value, vr, MV * EMBED);

    // main: weight transpose, then signal s1
    transpose_all<<<dim3(32, 32, 6), dim3(32, 8)>>>(Wo, Wa, Wv, Wp, Wf1, Wf2, wt);
    cudaEventRecord(evT, 0);
    cudaStreamWaitEvent(s1, evT, 0);

    // s1: value projection -> bf16 (198 tiles)
    gemm_bf16<<<198, 256, SM_BYTES, s1>>>(vr, wt + WT_V, bv, nullptr,
                                          nullptr, nullptr, nullptr, v,
                                          MV, 256, 256, 0);
    cudaEventRecord(evV, s1);

    // main: LN1 then fused offsets+logits GEMM (384 tiles -> persistent 296)
    ln_kernel<<<2048, 256>>>(query, g1, b1, qpos, qn, qa);
    gemm_bf16<<<296, 256, SM_BYTES>>>(qa, wt + WT_OA, bo, ba, nullptr,
                                      nullptr, oa, nullptr, BQ, 288, 256, 0);

    // join: sampling needs v (s1) and oa (main)
    cudaStreamWaitEvent(0, evV, 0);
    sample_kernel<<<(BQ * HEADS * 32) / 256, 256>>>(v, oa, refp, samp);

    // q = samp @ Wp + bp + qn + query (256 tiles)
    gemm_bf16<<<256, 256, SM_BYTES>>>(samp, wt + WT_P, bp, nullptr, qn, query,
                                      q, nullptr, BQ, 256, 256, 0);

    // q2 = bf16(LN2(q))
    ln_kernel<<<2048, 256>>>(q, g2, b2, nullptr, nullptr, q2);

    // hid = bf16(gelu(q2 @ Wf1 + bf1))  (1024 tiles -> persistent 296)
    gemm_bf16<<<296, 256, SM_BYTES>>>(q2, wt + WT_F1, bf1, nullptr, nullptr,
                                      nullptr, nullptr, hid, BQ, 1024, 256, 1);

    // out = q + hid @ Wf2 + bf2 (256 tiles)
    gemm_bf16<<<256, 256, SM_BYTES>>>(hid, wt + WT_F2, bf2, nullptr, q, nullptr,
                                      out, nullptr, BQ, 256, 1024, 0);
}